// round 8
// baseline (speedup 1.0000x reference)
#include <cuda_runtime.h>

// RNN_33964601377372: h_{t+1} = relu(x_t*W_ih + b_ih + b_hh + W_hh h_t), out = fc(h_T)
//
// L=8 row-split: 8 lanes per batch; lane e owns rows {e, e+8} and (e<4) e+16.
// Lanes e>=4 carry a dummy third row duplicating row e (same weights -> same
// value -> same-address store; keeps warp uniform). h exchanged via per-warp
// shared memory (stride 24 floats = conflict-free for both the 16B broadcast
// reads and all three scatter-store phases). Each row's dot product is one
// 10-deep FFMA2 chain over 10 (h2k,h2k+1) pairs loaded directly as u64 pairs.
// block=256, grid=128 -> 2 warps per SMSP uniformly: step is issue-bound at
// ~2x60 slots ~ 126 cyc instead of single-warp latency-bound ~206.

#define HID 20

typedef unsigned long long u64;

__device__ __forceinline__ u64 pack2(float lo, float hi) {
    u64 r; asm("mov.b64 %0, {%1, %2};" : "=l"(r) : "f"(lo), "f"(hi)); return r;
}
__device__ __forceinline__ u64 dup2(float v) {
    u64 r; asm("mov.b64 %0, {%1, %1};" : "=l"(r) : "f"(v)); return r;
}
__device__ __forceinline__ void unpack2(u64 p, float& lo, float& hi) {
    asm("mov.b64 {%0, %1}, %2;" : "=f"(lo), "=f"(hi) : "l"(p));
}
__device__ __forceinline__ u64 ffma2(u64 a, u64 b, u64 c) {
    u64 d; asm("fma.rn.f32x2 %0, %1, %2, %3;" : "=l"(d) : "l"(a), "l"(b), "l"(c)); return d;
}
__device__ __forceinline__ void lds_v2u64(unsigned addr, u64& a, u64& b) {
    asm volatile("ld.shared.v2.u64 {%0, %1}, [%2];" : "=l"(a), "=l"(b) : "r"(addr));
}
__device__ __forceinline__ void sts_f32(unsigned addr, float v) {
    asm volatile("st.shared.f32 [%0], %1;" :: "r"(addr), "f"(v));
}
__device__ __forceinline__ float lds_f32(unsigned addr) {
    float v; asm volatile("ld.shared.f32 %0, [%1];" : "=f"(v) : "r"(addr)); return v;
}

__global__ __launch_bounds__(256) void rnn_fused_kernel(
    const float* __restrict__ x,    // [B, T]
    const float* __restrict__ Wih,  // [H]
    const float* __restrict__ Whh,  // [H, H] row-major
    const float* __restrict__ bih,  // [H]
    const float* __restrict__ bhh,  // [H]
    const float* __restrict__ fcw,  // [H]
    const float* __restrict__ fcb,  // [1]
    float* __restrict__ out,        // [B]
    int B, int T)
{
    // 32 batches per CTA, h row padded to 24 floats (96B) for bank layout.
    __shared__ float hbuf[32][24];

    const int lt = threadIdx.x;
    const int g  = lt >> 3;            // batch within CTA (0..31)
    const int e  = lt & 7;             // lane within batch group
    int batch = blockIdx.x * 32 + g;
    const bool real = (batch < B);
    if (!real) batch = B - 1;          // clamp; lane stays resident

    // Owned rows; lanes e>=4 duplicate row e as the third (harmless rewrite).
    const int r_[3] = { e, 8 + e, (e < 4) ? 16 + e : e };

    // j-packed weights per owned row: wJ[r][k] = (Whh[row][2k], Whh[row][2k+1])
    u64 wJ[3][10];
#pragma unroll
    for (int r = 0; r < 3; ++r)
#pragma unroll
        for (int k = 0; k < 10; ++k)
            wJ[r][k] = pack2(Whh[r_[r] * HID + 2 * k],
                             Whh[r_[r] * HID + 2 * k + 1]);

    // x-projection + bias folded into chain seed (lo half carries the scalar).
    u64 wihP[3], biasP[3];
#pragma unroll
    for (int r = 0; r < 3; ++r) {
        wihP[r]  = pack2(Wih[r_[r]], 0.0f);
        biasP[r] = pack2(bih[r_[r]] + bhh[r_[r]], 0.0f);
    }

    const unsigned sbase =
        (unsigned)__cvta_generic_to_shared(&hbuf[g][0]);   // 96B stride, 16B aligned

    // h(0) = 0
#pragma unroll
    for (int r = 0; r < 3; ++r) sts_f32(sbase + 4u * r_[r], 0.0f);
    __syncwarp();

    const float* xb = x + (size_t)batch * T;    // 4000B stride, 16B-aligned
    const float4* xb4 = (const float4*)xb;
    const int nChunks = T >> 2;

    float4 xv = (nChunks > 0) ? xb4[0] : make_float4(0.f, 0.f, 0.f, 0.f);
    float4 xnext = xv;

    auto step = [&](float xt) {
        u64 xt2 = dup2(xt);
        u64 acc[3];
#pragma unroll
        for (int r = 0; r < 3; ++r)
            acc[r] = ffma2(xt2, wihP[r], biasP[r]);   // independent of LDS

        __syncwarp();                  // order previous step's STS before LDS
        u64 hp[10];
#pragma unroll
        for (int i = 0; i < 5; ++i)
            lds_v2u64(sbase + 16u * i, hp[2 * i], hp[2 * i + 1]);

#pragma unroll
        for (int k = 0; k < 10; ++k)
#pragma unroll
            for (int r = 0; r < 3; ++r)
                acc[r] = ffma2(hp[k], wJ[r][k], acc[r]);

#pragma unroll
        for (int r = 0; r < 3; ++r) {
            float lo, hi;
            unpack2(acc[r], lo, hi);
            sts_f32(sbase + 4u * r_[r], fmaxf(lo + hi, 0.0f));
        }
    };

    for (int c = 0; c < nChunks; ++c) {
        if (c + 1 < nChunks) xnext = xb4[c + 1];    // 4 steps of load hiding
        step(xv.x);
        step(xv.y);
        step(xv.z);
        step(xv.w);
        xv = xnext;
    }
    for (int t = nChunks << 2; t < T; ++t) step(xb[t]);  // tail (unused @T=1000)

    __syncwarp();

    // Head: out[b] = h . fc_w + fc_b. Lane partials over owned rows (dummy
    // third row masked), then xor-reduce across the 8-lane group.
    float p = lds_f32(sbase + 4u * r_[0]) * fcw[r_[0]]
            + lds_f32(sbase + 4u * r_[1]) * fcw[r_[1]];
    if (e < 4) p += lds_f32(sbase + 4u * r_[2]) * fcw[r_[2]];
    p += __shfl_xor_sync(0xffffffffu, p, 1, 8);
    p += __shfl_xor_sync(0xffffffffu, p, 2, 8);
    p += __shfl_xor_sync(0xffffffffu, p, 4, 8);
    if (e == 0 && real) out[batch] = p + fcb[0];
}

extern "C" void kernel_launch(void* const* d_in, const int* in_sizes, int n_in,
                              void* d_out, int out_size)
{
    const float* x    = (const float*)d_in[0];
    const float* Wih  = (const float*)d_in[1];
    const float* Whh  = (const float*)d_in[2];
    const float* bih  = (const float*)d_in[3];
    const float* bhh  = (const float*)d_in[4];
    const float* fcw  = (const float*)d_in[5];
    const float* fcb  = (const float*)d_in[6];
    float* out = (float*)d_out;

    int B = out_size;
    int T = in_sizes[0] / B;

    const int threads = 256;            // 8 warps -> 2 per SMSP; 32 batches/CTA
    int blocks = (B + 31) / 32;         // 128 CTAs at B=4096
    rnn_fused_kernel<<<blocks, threads>>>(x, Wih, Whh, bih, bhh, fcw, fcb, out, B, T);
}